// round 1
// baseline (speedup 1.0000x reference)
#include <cuda_runtime.h>
#include <math.h>

#define N0 4096
#define CH 256
#define EMAXED 131072

// ---------------- scratch (static device globals; no allocation) ----------------
static __device__ float g_A[(size_t)N0 * N0];    // 64MB: augment outputs
static __device__ float g_Ap[2048 * 2048];       // 16MB: pooled adjacency
static __device__ float g_fA[N0 * CH];           // features
static __device__ float g_fB[N0 * CH];           // features / B
static __device__ float g_xw[N0 * CH];           // scaled XW
static __device__ float g_dinv[N0];
static __device__ float g_score[N0];
static __device__ int   g_perm[N0];
static __device__ int   g_rowptr[N0 + 1];
static __device__ int   g_rowcnt[N0];
static __device__ int   g_rowcur[N0];
static __device__ int   g_cols[EMAXED];
static __device__ int   g_cntdiag[N0];
static __device__ int   g_indeg[N0];
static __device__ float g_pnorm;
static __device__ unsigned g_thr;
static __device__ int   g_cntgt;
static __device__ int   g_c0, g_c1;

__device__ __forceinline__ unsigned fkey(float f) {
    unsigned u = __float_as_uint(f);
    return (u & 0x80000000u) ? ~u : (u | 0x80000000u);
}

// ---------------- small utility kernels ----------------
__global__ void k_zero_counts() {
    int i = blockIdx.x * blockDim.x + threadIdx.x;
    if (i < N0) { g_rowcnt[i] = 0; g_rowcur[i] = 0; g_cntdiag[i] = 0; g_indeg[i] = 0; }
}

__global__ void k_edge_count(const int* __restrict__ ei, int E) {
    int e = blockIdx.x * blockDim.x + threadIdx.x;
    if (e >= E) return;
    int s = ei[e], d = ei[e + E];
    atomicAdd(&g_indeg[d], 1);
    if (s == d) atomicAdd(&g_cntdiag[s], 1);
    else        atomicAdd(&g_rowcnt[s], 1);
}

__global__ void k_scan() {  // exclusive scan of g_rowcnt[0..4095] -> g_rowptr; 1 block, 1024 thr
    __shared__ int sm[1024];
    int t = threadIdx.x;
    int b = t * 4;
    int v0 = g_rowcnt[b], v1 = g_rowcnt[b + 1], v2 = g_rowcnt[b + 2], v3 = g_rowcnt[b + 3];
    int tsum = v0 + v1 + v2 + v3;
    sm[t] = tsum; __syncthreads();
    for (int off = 1; off < 1024; off <<= 1) {
        int x = (t >= off) ? sm[t - off] : 0;
        __syncthreads();
        sm[t] += x;
        __syncthreads();
    }
    int excl = sm[t] - tsum;
    g_rowptr[b]     = excl;
    g_rowptr[b + 1] = excl + v0;
    g_rowptr[b + 2] = excl + v0 + v1;
    g_rowptr[b + 3] = excl + v0 + v1 + v2;
    if (t == 1023) g_rowptr[N0] = excl + tsum;
}

__global__ void k_edge_fill(const int* __restrict__ ei, int E) {
    int e = blockIdx.x * blockDim.x + threadIdx.x;
    if (e >= E) return;
    int s = ei[e], d = ei[e + E];
    if (s != d) {
        int pos = g_rowptr[s] + atomicAdd(&g_rowcur[s], 1);
        g_cols[pos] = d;
    }
}

__global__ void k_dinv0() {
    int j = blockIdx.x * blockDim.x + threadIdx.x;
    if (j >= N0) return;
    float deg = (float)g_indeg[j] + ((g_cntdiag[j] == 0) ? 2.0f : 0.0f);
    g_dinv[j] = rsqrtf(deg);
}

// ---------------- GEMM kernels: 64x64 tile, BK=16, 256 threads, 4x4 per thread -------
__global__ void k_gemm_xw(const float* __restrict__ A, const float* __restrict__ B,
                          float* __restrict__ Cm, int M, int useScale) {
    // C[M x 256] = A[M x 256] @ B[256 x 256]; optional row scale by g_dinv
    __shared__ float As[16][64];
    __shared__ float Bs[16][64];
    int tid = threadIdx.x;
    int tx = tid & 15, ty = tid >> 4;
    int i0 = blockIdx.y * 64, j0 = blockIdx.x * 64;
    float acc[16];
#pragma unroll
    for (int q = 0; q < 16; q++) acc[q] = 0.f;
    int r  = tid >> 2, c4 = (tid & 3) * 4;
    int kb = tid >> 4, jb4 = (tid & 15) * 4;
    for (int k0 = 0; k0 < 256; k0 += 16) {
        float4 av = *(const float4*)&A[(size_t)(i0 + r) * 256 + k0 + c4];
        As[c4 + 0][r] = av.x; As[c4 + 1][r] = av.y; As[c4 + 2][r] = av.z; As[c4 + 3][r] = av.w;
        *(float4*)&Bs[kb][jb4] = *(const float4*)&B[(size_t)(k0 + kb) * 256 + j0 + jb4];
        __syncthreads();
#pragma unroll
        for (int kk = 0; kk < 16; kk++) {
            float4 a = *(float4*)&As[kk][ty * 4];
            float4 b = *(float4*)&Bs[kk][tx * 4];
            acc[0]  += a.x * b.x; acc[1]  += a.x * b.y; acc[2]  += a.x * b.z; acc[3]  += a.x * b.w;
            acc[4]  += a.y * b.x; acc[5]  += a.y * b.y; acc[6]  += a.y * b.z; acc[7]  += a.y * b.w;
            acc[8]  += a.z * b.x; acc[9]  += a.z * b.y; acc[10] += a.z * b.z; acc[11] += a.z * b.w;
            acc[12] += a.w * b.x; acc[13] += a.w * b.y; acc[14] += a.w * b.z; acc[15] += a.w * b.w;
        }
        __syncthreads();
    }
#pragma unroll
    for (int ii = 0; ii < 4; ii++) {
        int gr = i0 + ty * 4 + ii;
        float sc = useScale ? g_dinv[gr] : 1.0f;
        float4 o;
        o.x = acc[ii * 4 + 0] * sc; o.y = acc[ii * 4 + 1] * sc;
        o.z = acc[ii * 4 + 2] * sc; o.w = acc[ii * 4 + 3] * sc;
        *(float4*)&Cm[(size_t)gr * 256 + j0 + tx * 4] = o;
    }
}

__global__ void k_gemm_AA(const float* __restrict__ A, float* __restrict__ Cm, int n) {
    // C = A @ A (n x n), epilogue zeros the diagonal
    __shared__ float As[16][64];
    __shared__ float Bs[16][64];
    int tid = threadIdx.x;
    int tx = tid & 15, ty = tid >> 4;
    int i0 = blockIdx.y * 64, j0 = blockIdx.x * 64;
    float acc[16];
#pragma unroll
    for (int q = 0; q < 16; q++) acc[q] = 0.f;
    int r  = tid >> 2, c4 = (tid & 3) * 4;
    int kb = tid >> 4, jb4 = (tid & 15) * 4;
    for (int k0 = 0; k0 < n; k0 += 16) {
        float4 av = *(const float4*)&A[(size_t)(i0 + r) * n + k0 + c4];
        As[c4 + 0][r] = av.x; As[c4 + 1][r] = av.y; As[c4 + 2][r] = av.z; As[c4 + 3][r] = av.w;
        *(float4*)&Bs[kb][jb4] = *(const float4*)&A[(size_t)(k0 + kb) * n + j0 + jb4];
        __syncthreads();
#pragma unroll
        for (int kk = 0; kk < 16; kk++) {
            float4 a = *(float4*)&As[kk][ty * 4];
            float4 b = *(float4*)&Bs[kk][tx * 4];
            acc[0]  += a.x * b.x; acc[1]  += a.x * b.y; acc[2]  += a.x * b.z; acc[3]  += a.x * b.w;
            acc[4]  += a.y * b.x; acc[5]  += a.y * b.y; acc[6]  += a.y * b.z; acc[7]  += a.y * b.w;
            acc[8]  += a.z * b.x; acc[9]  += a.z * b.y; acc[10] += a.z * b.z; acc[11] += a.z * b.w;
            acc[12] += a.w * b.x; acc[13] += a.w * b.y; acc[14] += a.w * b.z; acc[15] += a.w * b.w;
        }
        __syncthreads();
    }
#pragma unroll
    for (int ii = 0; ii < 4; ii++) {
        int gr = i0 + ty * 4 + ii;
        int gc0 = j0 + tx * 4;
        float4 o;
        o.x = acc[ii * 4 + 0]; o.y = acc[ii * 4 + 1]; o.z = acc[ii * 4 + 2]; o.w = acc[ii * 4 + 3];
        if (gr == gc0)     o.x = 0.f;
        if (gr == gc0 + 1) o.y = 0.f;
        if (gr == gc0 + 2) o.z = 0.f;
        if (gr == gc0 + 3) o.w = 0.f;
        *(float4*)&Cm[(size_t)gr * n + gc0] = o;
    }
}

__global__ void k_gemm_agg(const float* __restrict__ A, const float* __restrict__ B,
                           float* __restrict__ Cm, int n, const float* __restrict__ bias) {
    // C[i,c] = relu(g_dinv[i] * sum_j A[j*n+i]*B[j*256+c] + bias[c])
    __shared__ float As[16][64];   // As[kk][ii] = A[(k0+kk)*n + i0+ii]
    __shared__ float Bs[16][64];
    int tid = threadIdx.x;
    int tx = tid & 15, ty = tid >> 4;
    int i0 = blockIdx.y * 64, j0 = blockIdx.x * 64;
    float acc[16];
#pragma unroll
    for (int q = 0; q < 16; q++) acc[q] = 0.f;
    int ka = tid >> 4, ia4 = (tid & 15) * 4;
    for (int k0 = 0; k0 < n; k0 += 16) {
        *(float4*)&As[ka][ia4] = *(const float4*)&A[(size_t)(k0 + ka) * n + i0 + ia4];
        *(float4*)&Bs[ka][ia4] = *(const float4*)&B[(size_t)(k0 + ka) * 256 + j0 + ia4];
        __syncthreads();
#pragma unroll
        for (int kk = 0; kk < 16; kk++) {
            float4 a = *(float4*)&As[kk][ty * 4];
            float4 b = *(float4*)&Bs[kk][tx * 4];
            acc[0]  += a.x * b.x; acc[1]  += a.x * b.y; acc[2]  += a.x * b.z; acc[3]  += a.x * b.w;
            acc[4]  += a.y * b.x; acc[5]  += a.y * b.y; acc[6]  += a.y * b.z; acc[7]  += a.y * b.w;
            acc[8]  += a.z * b.x; acc[9]  += a.z * b.y; acc[10] += a.z * b.z; acc[11] += a.z * b.w;
            acc[12] += a.w * b.x; acc[13] += a.w * b.y; acc[14] += a.w * b.z; acc[15] += a.w * b.w;
        }
        __syncthreads();
    }
#pragma unroll
    for (int ii = 0; ii < 4; ii++) {
        int gr = i0 + ty * 4 + ii;
        float di = g_dinv[gr];
        float4 o;
        o.x = fmaxf(di * acc[ii * 4 + 0] + bias[j0 + tx * 4 + 0], 0.f);
        o.y = fmaxf(di * acc[ii * 4 + 1] + bias[j0 + tx * 4 + 1], 0.f);
        o.z = fmaxf(di * acc[ii * 4 + 2] + bias[j0 + tx * 4 + 2], 0.f);
        o.w = fmaxf(di * acc[ii * 4 + 3] + bias[j0 + tx * 4 + 3], 0.f);
        *(float4*)&Cm[(size_t)gr * 256 + j0 + tx * 4] = o;
    }
}

// ---------------- level-0 GCN aggregation (edge scatter) ----------------
__global__ void k_init_acc0(const float* __restrict__ Bf, float* __restrict__ acc) {
    int idx = blockIdx.x * blockDim.x + threadIdx.x;
    if (idx >= N0 * CH) return;
    int i = idx >> 8;
    float extra = (g_cntdiag[i] == 0) ? 2.0f : 0.0f;
    acc[idx] = extra * Bf[idx];
}

__global__ void k_scatter(const int* __restrict__ ei, int E,
                          const float* __restrict__ Bf, float* __restrict__ acc) {
    int e = blockIdx.x;
    int s = ei[e], d = ei[e + E];
    int t = threadIdx.x;
    atomicAdd(&acc[(size_t)d * CH + t], Bf[(size_t)s * CH + t]);
}

__global__ void k_gcn_epi(float* __restrict__ acc, const float* __restrict__ bias, int n) {
    int idx = blockIdx.x * blockDim.x + threadIdx.x;
    if (idx >= n * CH) return;
    int i = idx >> 8, c = idx & 255;
    acc[idx] = fmaxf(g_dinv[i] * acc[idx] + bias[c], 0.0f);
}

// ---------------- sparse augment at level 0: A2 = (E+I)^2, diag zeroed ----------------
__global__ void k_augment1(float* __restrict__ Am) {
    __shared__ float s[N0];
    int i = blockIdx.x;
    int t = threadIdx.x;
    for (int c = t; c < N0; c += 256) s[c] = 0.f;
    __syncthreads();
    int lane = t & 31, w = t >> 5;
    int beg = g_rowptr[i], end = g_rowptr[i + 1];
    for (int e = beg + w; e < end; e += 8) {
        int kc = g_cols[e];
        if (lane == 0) atomicAdd(&s[kc], 2.0f);
        int kb = g_rowptr[kc], ke = g_rowptr[kc + 1];
        for (int f = kb + lane; f < ke; f += 32) atomicAdd(&s[g_cols[f]], 1.0f);
    }
    __syncthreads();
    float* row = Am + (size_t)i * N0;
    for (int c = t; c < N0; c += 256) row[c] = (c == i) ? 0.0f : s[c];
}

// ---------------- pooling ----------------
__global__ void k_pnorm(const float* __restrict__ p) {
    __shared__ float red[256];
    int t = threadIdx.x;
    float v = p[t];
    red[t] = v * v;
    __syncthreads();
    for (int off = 128; off > 0; off >>= 1) { if (t < off) red[t] += red[t + off]; __syncthreads(); }
    if (t == 0) g_pnorm = sqrtf(red[0]);
}

__global__ void k_score(const float* __restrict__ F, const float* __restrict__ p, int n) {
    int w = threadIdx.x >> 5, lane = threadIdx.x & 31;
    int row = blockIdx.x * 8 + w;
    if (row >= n) return;
    float s = 0.f;
    for (int c = lane; c < CH; c += 32) s += F[(size_t)row * CH + c] * p[c];
#pragma unroll
    for (int off = 16; off; off >>= 1) s += __shfl_down_sync(0xffffffffu, s, off);
    if (lane == 0) g_score[row] = tanhf(s / g_pnorm);
}

__global__ void k_thresh(int n, int k) {  // 1 block, 1024 threads
    __shared__ unsigned u[N0];
    __shared__ int red[1024];
    int t = threadIdx.x;
    for (int i = t; i < n; i += 1024) u[i] = fkey(g_score[i]);
    __syncthreads();
    unsigned thr = 0;
    for (int bit = 31; bit >= 0; --bit) {
        unsigned cand = thr | (1u << bit);
        int c = 0;
        for (int i = t; i < n; i += 1024) if (u[i] >= cand) c++;
        red[t] = c; __syncthreads();
        for (int off = 512; off > 0; off >>= 1) { if (t < off) red[t] += red[t + off]; __syncthreads(); }
        int total = red[0];
        __syncthreads();
        if (total >= k) thr = cand;
    }
    int c = 0;
    for (int i = t; i < n; i += 1024) if (u[i] > thr) c++;
    red[t] = c; __syncthreads();
    for (int off = 512; off > 0; off >>= 1) { if (t < off) red[t] += red[t + off]; __syncthreads(); }
    if (t == 0) { g_thr = thr; g_cntgt = red[0]; g_c0 = 0; g_c1 = 0; }
}

__global__ void k_collect(int n, int k) {
    int i = blockIdx.x * blockDim.x + threadIdx.x;
    if (i >= n) return;
    unsigned u = fkey(g_score[i]);
    if (u > g_thr) {
        int p = atomicAdd(&g_c0, 1);
        g_perm[p] = i;
    } else if (u == g_thr) {
        int p = atomicAdd(&g_c1, 1);
        int pos = g_cntgt + p;
        if (pos < k) g_perm[pos] = i;
    }
}

__global__ void k_gather_x(const float* __restrict__ src, float* __restrict__ dst, int k) {
    int idx = blockIdx.x * blockDim.x + threadIdx.x;
    if (idx >= k * CH) return;
    int r = idx >> 8, c = idx & 255;
    int p = g_perm[r];
    dst[idx] = src[(size_t)p * CH + c] * g_score[p];
}

__global__ void k_gather_A(int k, int nold, const float* __restrict__ src, float* __restrict__ dst) {
    __shared__ int sp[2048];
    int r = blockIdx.x;
    for (int c = threadIdx.x; c < k; c += blockDim.x) sp[c] = g_perm[c];
    __syncthreads();
    int p = sp[r];
    const float* srow = src + (size_t)p * nold;
    float* drow = dst + (size_t)r * k;
    for (int c = threadIdx.x; c < k; c += blockDim.x) drow[c] = srow[sp[c]];
}

// ---------------- dense-level helpers ----------------
__global__ void k_setdiag(float* __restrict__ Am, int n, float v) {
    int i = blockIdx.x * blockDim.x + threadIdx.x;
    if (i < n) Am[(size_t)i * n + i] = v;
}

__global__ void k_colsum_dinv(const float* __restrict__ Am, int n) {
    int j = blockIdx.x * blockDim.x + threadIdx.x;
    if (j >= n) return;
    float s = 0.f;
    for (int r = 0; r < n; r++) s += Am[(size_t)r * n + j];
    g_dinv[j] = rsqrtf(s);
}

// ---------------- final readout ----------------
__global__ void k_final(const float* __restrict__ F, int n, const float* __restrict__ wc,
                        const float* __restrict__ bc, float* __restrict__ out, int out_size) {
    __shared__ float red[256];
    __shared__ float lg[16];
    int t = threadIdx.x;
    float s = 0.f;
    for (int r = 0; r < n; r++) s += F[(size_t)r * CH + t];
    float mv = s / (float)n;
    red[t] = mv * mv; __syncthreads();
    for (int off = 128; off > 0; off >>= 1) { if (t < off) red[t] += red[t + off]; __syncthreads(); }
    float nrm = fmaxf(sqrtf(red[0]), 1e-12f);
    __syncthreads();
    float e = mv / nrm;
    for (int j = 0; j < 10; j++) {
        red[t] = e * wc[j * CH + t]; __syncthreads();
        for (int off = 128; off > 0; off >>= 1) { if (t < off) red[t] += red[t + off]; __syncthreads(); }
        if (t == 0) lg[j] = red[0] + bc[j];
        __syncthreads();
    }
    if (t == 0) {
        float mx = lg[0];
        for (int j = 1; j < 10; j++) mx = fmaxf(mx, lg[j]);
        float se = 0.f;
        for (int j = 0; j < 10; j++) se += expf(lg[j] - mx);
        float lse = logf(se) + mx;
        for (int j = 0; j < 10; j++) lg[j] -= lse;
    }
    __syncthreads();
    if (t < out_size && t < CH) out[t] = e;
    if (t < 10 && CH + t < out_size) out[CH + t] = lg[t];
    // defensively clear any extra slots beyond 266
    for (int idx = 266 + t; idx < out_size; idx += 256) out[idx] = 0.0f;
}

// ---------------- launch ----------------
extern "C" void kernel_launch(void* const* d_in, const int* in_sizes, int n_in,
                              void* d_out, int out_size) {
    const float* x  = (const float*)d_in[0];
    const int*   ei = (const int*)d_in[1];
    const float* w0 = (const float*)d_in[2];
    const float* b0 = (const float*)d_in[3];
    const float* w1 = (const float*)d_in[4];
    const float* b1 = (const float*)d_in[5];
    const float* w2 = (const float*)d_in[6];
    const float* b2 = (const float*)d_in[7];
    const float* p1 = (const float*)d_in[8];
    const float* p2 = (const float*)d_in[9];
    const float* wc = (const float*)d_in[10];
    const float* bc = (const float*)d_in[11];
    float* out = (float*)d_out;
    int E = in_sizes[1] / 2;
    const int n0 = N0, k1 = 2048, k2 = 1024;

    float *pA, *pAp, *pfA, *pfB, *pxw;
    cudaGetSymbolAddress((void**)&pA,  g_A);
    cudaGetSymbolAddress((void**)&pAp, g_Ap);
    cudaGetSymbolAddress((void**)&pfA, g_fA);
    cudaGetSymbolAddress((void**)&pfB, g_fB);
    cudaGetSymbolAddress((void**)&pxw, g_xw);

    // ---- graph build + CSR ----
    k_zero_counts<<<(N0 + 255) / 256, 256>>>();
    k_edge_count<<<(E + 255) / 256, 256>>>(ei, E);
    k_scan<<<1, 1024>>>();
    k_edge_fill<<<(E + 255) / 256, 256>>>(ei, E);

    // ---- GCN level 0 (sparse scatter) ----
    k_dinv0<<<(N0 + 255) / 256, 256>>>();
    dim3 gx0(CH / 64, n0 / 64);
    k_gemm_xw<<<gx0, 256>>>(x, w0, pfB, n0, 1);           // B0 = dinv * (x @ w0)
    k_init_acc0<<<(n0 * CH + 255) / 256, 256>>>(pfB, pfA);
    k_scatter<<<E, 256>>>(ei, E, pfB, pfA);
    k_gcn_epi<<<(n0 * CH + 255) / 256, 256>>>(pfA, b0, n0);  // F0 in g_fA

    // ---- augment level 1 (sparse) ----
    k_augment1<<<n0, 256>>>(pA);

    // ---- pool 1 ----
    k_pnorm<<<1, 256>>>(p1);
    k_score<<<n0 / 8, 256>>>(pfA, p1, n0);
    k_thresh<<<1, 1024>>>(n0, k1);
    k_collect<<<(n0 + 255) / 256, 256>>>(n0, k1);
    k_gather_x<<<(k1 * CH + 255) / 256, 256>>>(pfA, pfB, k1);   // X1 in g_fB
    k_gather_A<<<k1, 256>>>(k1, n0, pA, pAp);                    // A1 in g_Ap

    // ---- GCN level 1 (dense) ----
    k_setdiag<<<(k1 + 255) / 256, 256>>>(pAp, k1, 2.0f);
    k_colsum_dinv<<<(k1 + 255) / 256, 256>>>(pAp, k1);
    dim3 gx1(CH / 64, k1 / 64);
    k_gemm_xw<<<gx1, 256>>>(pfB, w1, pxw, k1, 1);
    k_gemm_agg<<<gx1, 256>>>(pAp, pxw, pfA, k1, b1);             // F1 in g_fA

    // ---- augment level 2 (dense) ----
    k_setdiag<<<(k1 + 255) / 256, 256>>>(pAp, k1, 1.0f);
    dim3 gAA(k1 / 64, k1 / 64);
    k_gemm_AA<<<gAA, 256>>>(pAp, pA, k1);                        // A2 (2048x2048) in g_A

    // ---- pool 2 ----
    k_pnorm<<<1, 256>>>(p2);
    k_score<<<k1 / 8, 256>>>(pfA, p2, k1);
    k_thresh<<<1, 1024>>>(k1, k2);
    k_collect<<<(k1 + 255) / 256, 256>>>(k1, k2);
    k_gather_x<<<(k2 * CH + 255) / 256, 256>>>(pfA, pfB, k2);    // X2 in g_fB
    k_gather_A<<<k2, 256>>>(k2, k1, pA, pAp);                    // A2p in g_Ap

    // ---- GCN level 2 (dense) ----
    k_setdiag<<<(k2 + 255) / 256, 256>>>(pAp, k2, 2.0f);
    k_colsum_dinv<<<(k2 + 255) / 256, 256>>>(pAp, k2);
    dim3 gx2(CH / 64, k2 / 64);
    k_gemm_xw<<<gx2, 256>>>(pfB, w2, pxw, k2, 1);
    k_gemm_agg<<<gx2, 256>>>(pAp, pxw, pfA, k2, b2);             // F2 in g_fA

    // ---- readout ----
    k_final<<<1, 256>>>(pfA, k2, wc, bc, out, out_size);
}